// round 14
// baseline (speedup 1.0000x reference)
#include <cuda_runtime.h>
#include <cuda_bf16.h>
#include <cuda_fp16.h>
#include <stdint.h>

#define N_NODES 100000
#define N_EDGES 1600000
#define D_IN    256
#define D_OUT   128
#define N_TILES ((N_NODES + 127) / 128)   // 782

// ---------------- device scratch (no allocations allowed) ----------------
__device__ uint32_t g_support_h[(size_t)N_NODES * (D_OUT / 2)];   // 25.6 MB
__device__ int   g_counts[N_NODES];
__device__ int   g_rowptr[N_NODES + 1];
__device__ int   g_cursor[N_NODES];
__device__ int2  g_sorted_cv[N_EDGES];
__device__ int   g_tile_ctr;                           // dynamic tile counter

#define SCAN_B 1024
#define NSB    ((N_NODES + SCAN_B - 1) / SCAN_B)       // 98
__device__ int   g_blocksums[NSB];

// ---------------- 1) fp16 HMMA GEMM: support = X @ W ---------------------
// 2 CTAs/SM x 256 threads; dynamic tile scheduling via g_tile_ctr.
#define WSTRIDE 132
#define ASTRIDE 20
#define W_U32   (128 * WSTRIDE)            // 16896
#define A_U32S  (128 * ASTRIDE)            // 2560
#define SM_TOTAL_B ((W_U32 + 2 * A_U32S) * 4)   // 88064 bytes per CTA

__device__ __forceinline__ uint32_t pack_h2(float f0, float f1) {
    uint32_t r;
    asm("cvt.rn.f16x2.f32 %0, %1, %2;" : "=r"(r) : "f"(f1), "f"(f0));
    return r;
}

__device__ __forceinline__ void mma_f16(float* d, const uint32_t* a, const uint32_t* b) {
    asm volatile(
        "mma.sync.aligned.m16n8k16.row.col.f32.f16.f16.f32 "
        "{%0,%1,%2,%3}, {%4,%5,%6,%7}, {%8,%9}, {%0,%1,%2,%3};"
        : "+f"(d[0]), "+f"(d[1]), "+f"(d[2]), "+f"(d[3])
        : "r"(a[0]), "r"(a[1]), "r"(a[2]), "r"(a[3]), "r"(b[0]), "r"(b[1]));
}

__global__ __launch_bounds__(256, 2)
void gemm_mma_kernel(const float* __restrict__ A, const float* __restrict__ W) {
    extern __shared__ uint32_t smem[];
    uint32_t* w_s   = smem;                // [128][WSTRIDE]
    uint32_t* a_buf = smem + W_U32;        // [2 stages][A_U32S]
    __shared__ int s_tile;

    const int tid    = threadIdx.x;
    const int wid    = tid >> 5;           // 0..7
    const int lane   = tid & 31;
    const int warp_m = wid & 3;
    const int warp_n = wid >> 2;
    const int g      = lane >> 2;
    const int c      = lane & 3;

    // ---- W prologue: fp32 -> fp16 pairs into SMEM ----
    for (int idx = tid; idx < D_IN * D_OUT; idx += 256) {
        const int n = idx & 127;
        const int k = idx >> 7;
        __half h = __float2half_rn(W[(size_t)k * D_OUT + n]);
        ((uint16_t*)&w_s[n * WSTRIDE + (k >> 1)])[k & 1] = *(uint16_t*)&h;
    }

    const int a_row  = tid >> 1;           // 0..127
    const int a_half = tid & 1;

    for (;;) {
        __syncthreads();                   // protects s_tile + a_buf reuse
        if (tid == 0) s_tile = atomicAdd(&g_tile_ctr, 1);
        __syncthreads();
        const int tile = s_tile;
        if (tile >= N_TILES) break;
        const int m0 = tile * 128;

        // ---- first k-block prefetch (exposed once per tile) ----
        float4 p0, p1, p2, p3;
        {
            const int gr = m0 + a_row;
            if (gr < N_NODES) {
                const float4* p = (const float4*)(A + (size_t)gr * D_IN + a_half * 16);
                p0 = p[0]; p1 = p[1]; p2 = p[2]; p3 = p[3];
            } else {
                p0 = p1 = p2 = p3 = make_float4(0.f, 0.f, 0.f, 0.f);
            }
        }

        float acc[2][8][4];
#pragma unroll
        for (int mt = 0; mt < 2; mt++)
#pragma unroll
            for (int nt = 0; nt < 8; nt++)
#pragma unroll
                for (int q = 0; q < 4; q++) acc[mt][nt][q] = 0.f;

        for (int kb = 0; kb < 8; kb++) {
            const int st = kb & 1;
            uint32_t* as = a_buf + st * A_U32S;

            // ---- convert prefetched regs + store to stage ----
            {
                uint4 t0 = make_uint4(pack_h2(p0.x, p0.y), pack_h2(p0.z, p0.w),
                                      pack_h2(p1.x, p1.y), pack_h2(p1.z, p1.w));
                uint4 t1 = make_uint4(pack_h2(p2.x, p2.y), pack_h2(p2.z, p2.w),
                                      pack_h2(p3.x, p3.y), pack_h2(p3.z, p3.w));
                uint32_t* d = as + a_row * ASTRIDE + a_half * 8;
                *(uint4*)(d + 0) = t0;
                *(uint4*)(d + 4) = t1;
            }

            // ---- prefetch next k-block (within tile) ----
            if (kb < 7) {
                const int gr = m0 + a_row;
                if (gr < N_NODES) {
                    const float4* p = (const float4*)(A + (size_t)gr * D_IN + (kb + 1) * 32 + a_half * 16);
                    p0 = p[0]; p1 = p[1]; p2 = p[2]; p3 = p[3];
                } else {
                    p0 = p1 = p2 = p3 = make_float4(0.f, 0.f, 0.f, 0.f);
                }
            }
            __syncthreads();

            // ---- compute: 2 k16 steps ----
#pragma unroll
            for (int kk = 0; kk < 2; kk++) {
                const int kpl = kk * 8 + c;
                const int kpg = kb * 16 + kk * 8 + c;

                uint32_t av[2][4];
#pragma unroll
                for (int mt = 0; mt < 2; mt++) {
                    const int r0 = (warp_m * 32 + mt * 16 + g) * ASTRIDE;
                    const int r1 = r0 + 8 * ASTRIDE;
                    av[mt][0] = as[r0 + kpl];
                    av[mt][1] = as[r1 + kpl];
                    av[mt][2] = as[r0 + kpl + 4];
                    av[mt][3] = as[r1 + kpl + 4];
                }
                uint32_t bv[8][2];
#pragma unroll
                for (int nt = 0; nt < 8; nt++) {
                    const int n = warp_n * 64 + nt * 8 + g;
                    bv[nt][0] = w_s[n * WSTRIDE + kpg];
                    bv[nt][1] = w_s[n * WSTRIDE + kpg + 4];
                }
#pragma unroll
                for (int mt = 0; mt < 2; mt++)
#pragma unroll
                    for (int nt = 0; nt < 8; nt++)
                        mma_f16(acc[mt][nt], av[mt], bv[nt]);
            }
        }

        // ---- epilogue: convert to fp16 (half2 per u32) ----
#pragma unroll
        for (int mt = 0; mt < 2; mt++) {
            const int r0 = m0 + warp_m * 32 + mt * 16 + g;
#pragma unroll
            for (int nt = 0; nt < 8; nt++) {
                const int u = warp_n * 32 + nt * 4 + c;
                if (r0 < N_NODES) {
                    __half2 h = __floats2half2_rn(acc[mt][nt][0], acc[mt][nt][1]);
                    g_support_h[(size_t)r0 * (D_OUT / 2) + u] = *(uint32_t*)&h;
                }
                if (r0 + 8 < N_NODES) {
                    __half2 h = __floats2half2_rn(acc[mt][nt][2], acc[mt][nt][3]);
                    g_support_h[(size_t)(r0 + 8) * (D_OUT / 2) + u] = *(uint32_t*)&h;
                }
            }
        }
    }
}

// ---------------- 2) CSR build: histogram -> scan -> scatter -------------
// 16 edges per thread: 4x int4 loads batched for MLP, then 16 REDs.
__global__ void hist16_kernel(const int* __restrict__ rows) {
    int t = blockIdx.x * blockDim.x + threadIdx.x;
    if (t >= N_EDGES / 16) return;
    const int4* r4 = (const int4*)rows + t * 4;
    int4 a = r4[0], b = r4[1], c = r4[2], d = r4[3];
    atomicAdd(&g_counts[a.x], 1); atomicAdd(&g_counts[a.y], 1);
    atomicAdd(&g_counts[a.z], 1); atomicAdd(&g_counts[a.w], 1);
    atomicAdd(&g_counts[b.x], 1); atomicAdd(&g_counts[b.y], 1);
    atomicAdd(&g_counts[b.z], 1); atomicAdd(&g_counts[b.w], 1);
    atomicAdd(&g_counts[c.x], 1); atomicAdd(&g_counts[c.y], 1);
    atomicAdd(&g_counts[c.z], 1); atomicAdd(&g_counts[c.w], 1);
    atomicAdd(&g_counts[d.x], 1); atomicAdd(&g_counts[d.y], 1);
    atomicAdd(&g_counts[d.z], 1); atomicAdd(&g_counts[d.w], 1);
}

__global__ __launch_bounds__(SCAN_B)
void scan1_kernel() {
    __shared__ int sh[SCAN_B];
    int i = blockIdx.x * SCAN_B + threadIdx.x;
    int v = (i < N_NODES) ? g_counts[i] : 0;
    sh[threadIdx.x] = v;
    __syncthreads();
#pragma unroll
    for (int off = 1; off < SCAN_B; off <<= 1) {
        int t = (threadIdx.x >= off) ? sh[threadIdx.x - off] : 0;
        __syncthreads();
        sh[threadIdx.x] += t;
        __syncthreads();
    }
    if (i < N_NODES) g_rowptr[i] = sh[threadIdx.x] - v;
    if (threadIdx.x == SCAN_B - 1) g_blocksums[blockIdx.x] = sh[SCAN_B - 1];
}

__global__ __launch_bounds__(256)
void scan23_kernel() {
    __shared__ int sh[256];
    const int t = threadIdx.x;
    const int v = (t < NSB) ? g_blocksums[t] : 0;
    sh[t] = v;
    __syncthreads();
#pragma unroll
    for (int off = 1; off < 256; off <<= 1) {
        int x = (t >= off) ? sh[t - off] : 0;
        __syncthreads();
        sh[t] += x;
        __syncthreads();
    }
    __shared__ int base;
    if (t == 0) {
        const int seg = (blockIdx.x * 256) / SCAN_B;
        base = sh[seg] - g_blocksums[seg];
    }
    __syncthreads();
    const int i = blockIdx.x * 256 + t;
    if (i < N_NODES) {
        const int val = g_rowptr[i] + base;
        g_rowptr[i] = val;
        g_cursor[i] = val;
    }
    if (i == 0) g_rowptr[N_NODES] = N_EDGES;
}

// 8 edges per thread
__global__ void scatter8_kernel(const int* __restrict__ rows,
                                const int* __restrict__ cols,
                                const float* __restrict__ vals) {
    int t = blockIdx.x * blockDim.x + threadIdx.x;
    if (t >= N_EDGES / 8) return;
    const int4*   r4 = (const int4*)rows + t * 2;
    const int4*   c4 = (const int4*)cols + t * 2;
    const float4* v4 = (const float4*)vals + t * 2;
    int4   ra = r4[0], rb = r4[1];
    int4   ca = c4[0], cb = c4[1];
    float4 va = v4[0], vb = v4[1];
    int p0 = atomicAdd(&g_cursor[ra.x], 1);
    int p1 = atomicAdd(&g_cursor[ra.y], 1);
    int p2 = atomicAdd(&g_cursor[ra.z], 1);
    int p3 = atomicAdd(&g_cursor[ra.w], 1);
    int p4 = atomicAdd(&g_cursor[rb.x], 1);
    int p5 = atomicAdd(&g_cursor[rb.y], 1);
    int p6 = atomicAdd(&g_cursor[rb.z], 1);
    int p7 = atomicAdd(&g_cursor[rb.w], 1);
    g_sorted_cv[p0] = make_int2(ca.x, __float_as_int(va.x));
    g_sorted_cv[p1] = make_int2(ca.y, __float_as_int(va.y));
    g_sorted_cv[p2] = make_int2(ca.z, __float_as_int(va.z));
    g_sorted_cv[p3] = make_int2(ca.w, __float_as_int(va.w));
    g_sorted_cv[p4] = make_int2(cb.x, __float_as_int(vb.x));
    g_sorted_cv[p5] = make_int2(cb.y, __float_as_int(vb.y));
    g_sorted_cv[p6] = make_int2(cb.z, __float_as_int(vb.z));
    g_sorted_cv[p7] = make_int2(cb.w, __float_as_int(vb.w));
}

// ---------------- 3) Aggregate: warp/row, shfl-broadcast edge data -------
__global__ __launch_bounds__(256)
void aggregate_kernel(const float* __restrict__ bias, float* __restrict__ out) {
    int w    = (blockIdx.x * blockDim.x + threadIdx.x) >> 5;
    int lane = threadIdx.x & 31;
    if (w >= N_NODES) return;

    const int s = g_rowptr[w];
    const int e = g_rowptr[w + 1];

    float4 acc = ((const float4*)bias)[lane];

    for (int base = s; base < e; base += 32) {
        const int rem = e - base;
        int2 cv = make_int2(0, 0);
        if (lane < rem) cv = g_sorted_cv[base + lane];
        const int n = rem < 32 ? rem : 32;

#pragma unroll 8
        for (int j = 0; j < n; j++) {
            const int   col = __shfl_sync(0xFFFFFFFFu, cv.x, j);
            const float v   = __int_as_float(__shfl_sync(0xFFFFFFFFu, cv.y, j));
            uint2 sv = *(const uint2*)&g_support_h[(size_t)col * 64 + lane * 2];
            float2 a = __half22float2(*(__half2*)&sv.x);
            float2 b = __half22float2(*(__half2*)&sv.y);
            acc.x += v * a.x; acc.y += v * a.y; acc.z += v * b.x; acc.w += v * b.y;
        }
    }

    *(float4*)&out[(size_t)w * D_OUT + lane * 4] = acc;
}

// ---------------- launch ------------------------------------------------
extern "C" void kernel_launch(void* const* d_in, const int* in_sizes, int n_in,
                              void* d_out, int out_size) {
    const float* in_feature = (const float*)d_in[0];
    const int*   edge_rows  = (const int*)d_in[1];
    const int*   edge_cols  = (const int*)d_in[2];
    const float* edge_vals  = (const float*)d_in[3];
    const float* weight     = (const float*)d_in[4];
    const float* bias       = (const float*)d_in[5];
    float*       out        = (float*)d_out;

    (void)in_sizes; (void)n_in; (void)out_size;

    static cudaStream_t s2 = 0;
    static cudaEvent_t ev_fork = 0, ev_join = 0;
    static void* counts_ptr = 0;
    static void* ctr_ptr = 0;
    static int init_done = 0;
    if (!init_done) {
        cudaFuncSetAttribute(gemm_mma_kernel, cudaFuncAttributeMaxDynamicSharedMemorySize, SM_TOTAL_B);
        cudaStreamCreateWithFlags(&s2, cudaStreamNonBlocking);
        cudaEventCreateWithFlags(&ev_fork, cudaEventDisableTiming);
        cudaEventCreateWithFlags(&ev_join, cudaEventDisableTiming);
        cudaGetSymbolAddress(&counts_ptr, g_counts);
        cudaGetSymbolAddress(&ctr_ptr, g_tile_ctr);
        init_done = 1;
    }

    // fork: CSR build (s2) runs concurrently with GEMM (main stream)
    cudaEventRecord(ev_fork, 0);
    cudaStreamWaitEvent(s2, ev_fork, 0);

    // --- s2: CSR build front half ---
    cudaMemsetAsync(counts_ptr, 0, N_NODES * sizeof(int), s2);
    hist16_kernel<<<(N_EDGES / 16 + 255) / 256, 256, 0, s2>>>(edge_rows);
    scan1_kernel<<<NSB, SCAN_B, 0, s2>>>();
    scan23_kernel<<<(N_NODES + 255) / 256, 256, 0, s2>>>();

    // --- main stream: tile counter reset + GEMM ---
    cudaMemsetAsync(ctr_ptr, 0, sizeof(int), 0);
    gemm_mma_kernel<<<296, 256, SM_TOTAL_B>>>(in_feature, weight);

    // --- s2: CSR back half ---
    scatter8_kernel<<<(N_EDGES / 8 + 255) / 256, 256, 0, s2>>>(edge_rows, edge_cols, edge_vals);

    // join
    cudaEventRecord(ev_join, s2);
    cudaStreamWaitEvent(0, ev_join, 0);

    // 3) out = A @ support + bias   (one warp per row)
    int blocks = (N_NODES * 32 + 255) / 256;
    aggregate_kernel<<<blocks, 256>>>(bias, out);
}

// round 15
// speedup vs baseline: 1.1035x; 1.1035x over previous
#include <cuda_runtime.h>
#include <cuda_bf16.h>
#include <cuda_fp16.h>
#include <stdint.h>

#define N_NODES 100000
#define N_EDGES 1600000
#define D_IN    256
#define D_OUT   128
#define N_TILES ((N_NODES + 127) / 128)   // 782

// ---------------- device scratch (no allocations allowed) ----------------
__device__ uint32_t g_support_h[(size_t)N_NODES * (D_OUT / 2)];   // 25.6 MB
__device__ int   g_counts[N_NODES];
__device__ int   g_rowptr[N_NODES + 1];
__device__ int   g_cursor[N_NODES];
__device__ int2  g_sorted_cv[N_EDGES];

#define SCAN_B 1024
#define NSB    ((N_NODES + SCAN_B - 1) / SCAN_B)       // 98
__device__ int   g_blocksums[NSB];

// ---------------- 1) fp16 HMMA GEMM: support = X @ W ---------------------
// 512 threads, 1 CTA/SM, 128x128 tile.  64-k double-stages: 4 A-buffers,
// one __syncthreads per 64 k (4 per tile instead of 8).
#define WSTRIDE 132
#define ASTRIDE 20
#define W_U32   (128 * WSTRIDE)            // 16896
#define A_U32S  (128 * ASTRIDE)            // 2560 (one 32-k block)
#define SM_TOTAL_B ((W_U32 + 4 * A_U32S) * 4)   // 108544 bytes

__device__ __forceinline__ uint32_t pack_h2(float f0, float f1) {
    uint32_t r;
    asm("cvt.rn.f16x2.f32 %0, %1, %2;" : "=r"(r) : "f"(f1), "f"(f0));
    return r;
}

__device__ __forceinline__ void mma_f16(float* d, const uint32_t* a, const uint32_t* b) {
    asm volatile(
        "mma.sync.aligned.m16n8k16.row.col.f32.f16.f16.f32 "
        "{%0,%1,%2,%3}, {%4,%5,%6,%7}, {%8,%9}, {%0,%1,%2,%3};"
        : "+f"(d[0]), "+f"(d[1]), "+f"(d[2]), "+f"(d[3])
        : "r"(a[0]), "r"(a[1]), "r"(a[2]), "r"(a[3]), "r"(b[0]), "r"(b[1]));
}

__global__ __launch_bounds__(512, 1)
void gemm_mma_kernel(const float* __restrict__ A, const float* __restrict__ W) {
    extern __shared__ uint32_t smem[];
    uint32_t* w_s   = smem;                // [128][WSTRIDE]
    uint32_t* a_buf = smem + W_U32;        // [4 blocks][A_U32S]: stage s = blocks 2s,2s+1

    const int tid    = threadIdx.x;
    const int wid    = tid >> 5;           // 0..15
    const int lane   = tid & 31;
    const int warp_m = wid & 3;            // 4 row-bands of 32
    const int warp_n = wid >> 2;           // 4 col-bands of 32
    const int g      = lane >> 2;
    const int c      = lane & 3;

    // ---- W prologue: fp32 -> fp16 pairs into SMEM ----
    for (int idx = tid; idx < D_IN * D_OUT; idx += 512) {
        const int n = idx & 127;
        const int k = idx >> 7;
        __half h = __float2half_rn(W[(size_t)k * D_OUT + n]);
        ((uint16_t*)&w_s[n * WSTRIDE + (k >> 1)])[k & 1] = *(uint16_t*)&h;
    }
    __syncthreads();

    const int a_row = tid >> 2;            // 0..127
    const int a_q   = tid & 3;             // 8-float quarter within each 32-k block

    // ---- register prefetch of one 64-k double-block ----
    float4 p0, p1, p2, p3;                 // p0,p1: first 32-k block; p2,p3: second
    {
        const int gr = blockIdx.x * 128 + a_row;
        if (blockIdx.x < N_TILES && gr < N_NODES) {
            const float4* q = (const float4*)(A + (size_t)gr * D_IN + a_q * 8);
            p0 = q[0]; p1 = q[1];
            const float4* q2 = (const float4*)(A + (size_t)gr * D_IN + 32 + a_q * 8);
            p2 = q2[0]; p3 = q2[1];
        } else {
            p0 = p1 = p2 = p3 = make_float4(0.f, 0.f, 0.f, 0.f);
        }
    }

    for (int tile = blockIdx.x; tile < N_TILES; tile += gridDim.x) {
        const int m0 = tile * 128;

        float acc[2][4][4];
#pragma unroll
        for (int mt = 0; mt < 2; mt++)
#pragma unroll
            for (int nt = 0; nt < 4; nt++)
#pragma unroll
                for (int q = 0; q < 4; q++) acc[mt][nt][q] = 0.f;

        for (int kbp = 0; kbp < 4; kbp++) {            // 64-k double-blocks
            const int st = kbp & 1;
            uint32_t* as0 = a_buf + (st * 2 + 0) * A_U32S;
            uint32_t* as1 = a_buf + (st * 2 + 1) * A_U32S;

            // ---- convert prefetched regs + store both 32-k blocks ----
            {
                uint4 t0 = make_uint4(pack_h2(p0.x, p0.y), pack_h2(p0.z, p0.w),
                                      pack_h2(p1.x, p1.y), pack_h2(p1.z, p1.w));
                uint4 t1 = make_uint4(pack_h2(p2.x, p2.y), pack_h2(p2.z, p2.w),
                                      pack_h2(p3.x, p3.y), pack_h2(p3.z, p3.w));
                *(uint4*)(as0 + a_row * ASTRIDE + a_q * 4) = t0;
                *(uint4*)(as1 + a_row * ASTRIDE + a_q * 4) = t1;
            }

            // ---- issue prefetch for next 64-k (or next tile) ----
            {
                int nk = kbp + 1, ntile = tile;
                if (nk == 4) { nk = 0; ntile = tile + gridDim.x; }
                const int gr = ntile * 128 + a_row;
                if (ntile < N_TILES && gr < N_NODES) {
                    const float* base = A + (size_t)gr * D_IN + nk * 64;
                    const float4* q  = (const float4*)(base + a_q * 8);
                    const float4* q2 = (const float4*)(base + 32 + a_q * 8);
                    p0 = q[0]; p1 = q[1]; p2 = q2[0]; p3 = q2[1];
                } else {
                    p0 = p1 = p2 = p3 = make_float4(0.f, 0.f, 0.f, 0.f);
                }
            }
            __syncthreads();

            // ---- compute: 4 k16 steps across the two blocks ----
#pragma unroll
            for (int q = 0; q < 4; q++) {
                uint32_t* as = (q < 2) ? as0 : as1;
                const int kpl = (q & 1) * 8 + c;            // local kpair in block
                const int kpg = kbp * 32 + q * 8 + c;       // global kpair for W

                uint32_t av[2][4];
#pragma unroll
                for (int mt = 0; mt < 2; mt++) {
                    const int r0 = (warp_m * 32 + mt * 16 + g) * ASTRIDE;
                    const int r1 = r0 + 8 * ASTRIDE;
                    av[mt][0] = as[r0 + kpl];
                    av[mt][1] = as[r1 + kpl];
                    av[mt][2] = as[r0 + kpl + 4];
                    av[mt][3] = as[r1 + kpl + 4];
                }
                uint32_t bv[4][2];
#pragma unroll
                for (int nt = 0; nt < 4; nt++) {
                    const int n = warp_n * 32 + nt * 8 + g;
                    bv[nt][0] = w_s[n * WSTRIDE + kpg];
                    bv[nt][1] = w_s[n * WSTRIDE + kpg + 4];
                }
#pragma unroll
                for (int mt = 0; mt < 2; mt++)
#pragma unroll
                    for (int nt = 0; nt < 4; nt++)
                        mma_f16(acc[mt][nt], av[mt], bv[nt]);
            }
        }

        // ---- epilogue: convert to fp16 (half2 per u32) ----
#pragma unroll
        for (int mt = 0; mt < 2; mt++) {
            const int r0 = m0 + warp_m * 32 + mt * 16 + g;
#pragma unroll
            for (int nt = 0; nt < 4; nt++) {
                const int u = warp_n * 16 + nt * 4 + c;
                if (r0 < N_NODES) {
                    __half2 h = __floats2half2_rn(acc[mt][nt][0], acc[mt][nt][1]);
                    g_support_h[(size_t)r0 * (D_OUT / 2) + u] = *(uint32_t*)&h;
                }
                if (r0 + 8 < N_NODES) {
                    __half2 h = __floats2half2_rn(acc[mt][nt][2], acc[mt][nt][3]);
                    g_support_h[(size_t)(r0 + 8) * (D_OUT / 2) + u] = *(uint32_t*)&h;
                }
            }
        }
        __syncthreads();
    }
}

// ---------------- 2) CSR build: histogram -> scan -> scatter -------------
__global__ void hist4_kernel(const int* __restrict__ rows) {
    int t = blockIdx.x * blockDim.x + threadIdx.x;
    if (t * 4 >= N_EDGES) return;
    int4 r = ((const int4*)rows)[t];
    atomicAdd(&g_counts[r.x], 1);
    atomicAdd(&g_counts[r.y], 1);
    atomicAdd(&g_counts[r.z], 1);
    atomicAdd(&g_counts[r.w], 1);
}

__global__ __launch_bounds__(SCAN_B)
void scan1_kernel() {
    __shared__ int sh[SCAN_B];
    int i = blockIdx.x * SCAN_B + threadIdx.x;
    int v = (i < N_NODES) ? g_counts[i] : 0;
    sh[threadIdx.x] = v;
    __syncthreads();
#pragma unroll
    for (int off = 1; off < SCAN_B; off <<= 1) {
        int t = (threadIdx.x >= off) ? sh[threadIdx.x - off] : 0;
        __syncthreads();
        sh[threadIdx.x] += t;
        __syncthreads();
    }
    if (i < N_NODES) g_rowptr[i] = sh[threadIdx.x] - v;
    if (threadIdx.x == SCAN_B - 1) g_blocksums[blockIdx.x] = sh[SCAN_B - 1];
}

__global__ __launch_bounds__(256)
void scan23_kernel() {
    __shared__ int sh[256];
    const int t = threadIdx.x;
    const int v = (t < NSB) ? g_blocksums[t] : 0;
    sh[t] = v;
    __syncthreads();
#pragma unroll
    for (int off = 1; off < 256; off <<= 1) {
        int x = (t >= off) ? sh[t - off] : 0;
        __syncthreads();
        sh[t] += x;
        __syncthreads();
    }
    __shared__ int base;
    if (t == 0) {
        const int seg = (blockIdx.x * 256) / SCAN_B;
        base = sh[seg] - g_blocksums[seg];
    }
    __syncthreads();
    const int i = blockIdx.x * 256 + t;
    if (i < N_NODES) {
        const int val = g_rowptr[i] + base;
        g_rowptr[i] = val;
        g_cursor[i] = val;
    }
    if (i == 0) g_rowptr[N_NODES] = N_EDGES;
}

__global__ void scatter4_kernel(const int* __restrict__ rows,
                                const int* __restrict__ cols,
                                const float* __restrict__ vals) {
    int t = blockIdx.x * blockDim.x + threadIdx.x;
    if (t * 4 >= N_EDGES) return;
    int4   r = ((const int4*)rows)[t];
    int4   c = ((const int4*)cols)[t];
    float4 v = ((const float4*)vals)[t];
    int p0 = atomicAdd(&g_cursor[r.x], 1);
    int p1 = atomicAdd(&g_cursor[r.y], 1);
    int p2 = atomicAdd(&g_cursor[r.z], 1);
    int p3 = atomicAdd(&g_cursor[r.w], 1);
    g_sorted_cv[p0] = make_int2(c.x, __float_as_int(v.x));
    g_sorted_cv[p1] = make_int2(c.y, __float_as_int(v.y));
    g_sorted_cv[p2] = make_int2(c.z, __float_as_int(v.z));
    g_sorted_cv[p3] = make_int2(c.w, __float_as_int(v.w));
}

// ---------------- 3) Aggregate: warp/row, shfl-broadcast edge data -------
__global__ __launch_bounds__(256)
void aggregate_kernel(const float* __restrict__ bias, float* __restrict__ out) {
    int w    = (blockIdx.x * blockDim.x + threadIdx.x) >> 5;
    int lane = threadIdx.x & 31;
    if (w >= N_NODES) return;

    const int s = g_rowptr[w];
    const int e = g_rowptr[w + 1];

    float4 acc = ((const float4*)bias)[lane];

    for (int base = s; base < e; base += 32) {
        const int rem = e - base;
        int2 cv = make_int2(0, 0);
        if (lane < rem) cv = g_sorted_cv[base + lane];
        const int n = rem < 32 ? rem : 32;

#pragma unroll 8
        for (int j = 0; j < n; j++) {
            const int   col = __shfl_sync(0xFFFFFFFFu, cv.x, j);
            const float v   = __int_as_float(__shfl_sync(0xFFFFFFFFu, cv.y, j));
            uint2 sv = *(const uint2*)&g_support_h[(size_t)col * 64 + lane * 2];
            float2 a = __half22float2(*(__half2*)&sv.x);
            float2 b = __half22float2(*(__half2*)&sv.y);
            acc.x += v * a.x; acc.y += v * a.y; acc.z += v * b.x; acc.w += v * b.y;
        }
    }

    *(float4*)&out[(size_t)w * D_OUT + lane * 4] = acc;
}

// ---------------- launch ------------------------------------------------
extern "C" void kernel_launch(void* const* d_in, const int* in_sizes, int n_in,
                              void* d_out, int out_size) {
    const float* in_feature = (const float*)d_in[0];
    const int*   edge_rows  = (const int*)d_in[1];
    const int*   edge_cols  = (const int*)d_in[2];
    const float* edge_vals  = (const float*)d_in[3];
    const float* weight     = (const float*)d_in[4];
    const float* bias       = (const float*)d_in[5];
    float*       out        = (float*)d_out;

    (void)in_sizes; (void)n_in; (void)out_size;

    static cudaStream_t s2 = 0;
    static cudaEvent_t ev_fork = 0, ev_join = 0;
    static void* counts_ptr = 0;
    static int init_done = 0;
    if (!init_done) {
        cudaFuncSetAttribute(gemm_mma_kernel, cudaFuncAttributeMaxDynamicSharedMemorySize, SM_TOTAL_B);
        cudaStreamCreateWithFlags(&s2, cudaStreamNonBlocking);
        cudaEventCreateWithFlags(&ev_fork, cudaEventDisableTiming);
        cudaEventCreateWithFlags(&ev_join, cudaEventDisableTiming);
        cudaGetSymbolAddress(&counts_ptr, g_counts);
        init_done = 1;
    }

    // fork: CSR build (s2) runs concurrently with GEMM (main stream)
    cudaEventRecord(ev_fork, 0);
    cudaStreamWaitEvent(s2, ev_fork, 0);

    // --- s2: CSR build front half ---
    cudaMemsetAsync(counts_ptr, 0, N_NODES * sizeof(int), s2);
    hist4_kernel<<<(N_EDGES / 4 + 255) / 256, 256, 0, s2>>>(edge_rows);
    scan1_kernel<<<NSB, SCAN_B, 0, s2>>>();
    scan23_kernel<<<(N_NODES + 255) / 256, 256, 0, s2>>>();

    // --- main stream: GEMM (ncu capture slot) ---
    gemm_mma_kernel<<<148, 512, SM_TOTAL_B>>>(in_feature, weight);

    // --- s2: CSR back half ---
    scatter4_kernel<<<(N_EDGES / 4 + 255) / 256, 256, 0, s2>>>(edge_rows, edge_cols, edge_vals);

    // join
    cudaEventRecord(ev_join, s2);
    cudaStreamWaitEvent(0, ev_join, 0);

    // 3) out = A @ support + bias   (one warp per row)
    int blocks = (N_NODES * 32 + 255) / 256;
    aggregate_kernel<<<blocks, 256>>>(bias, out);
}